// round 12
// baseline (speedup 1.0000x reference)
#include <cuda_runtime.h>
#include <cstdint>

// FSMN depthwise strided FIR on GB300 — R12.
// Pipe accounting across R5/R9/R11 (all ~80us): FMA-pipe time ~39us and
// smem-crossbar time ~36us (9.4 LDS.64/output), nearly serialized. Fix:
// raise in-register reuse with RT=16 (one parity per thread) -> 7.0
// LDS/output (-26% crossbar). The old RT=16 blocker was the 128-reg cap at
// 256-512 thr blocks; with 192-thread blocks x 2/SM ptxas gets a 170-reg
// budget, so acc[16]+w[16] fits with NO spill. Scaffold = R11 (smem filter
// slab, double-buffered cp.async x fill).
//
// out[b,t,d] = sum_{i=0..19} filt[i,d]*x[b,t-(20-i)*2,d]
//            + filt[20,d]*x[b,t,d]
//            + sum_{j=0..19} filt[21+j,d]*x[b,t+1+2j,d],  zero-padded.

#define B_   32
#define T_   2000
#define DPAL 256        // d-pairs across all of D
#define DPB  32         // d-pairs per block
#define RT   16         // outputs per thread (one parity, stride 2 -> 32 t)
#define NTH  192        // 32 dpl x 2 par x 3 groups
#define TT   96         // t-outputs per tile (3 groups x 32)
#define TPB  7          // tiles per block; grid.x=3 -> 21 tiles (2016>=2000)
#define ROWS (TT + 80)  // 176 smem rows per tile
#define XWORDS (ROWS * DPB)            // 5632 u64 per buffer
#define XBYTES (XWORDS * 8)            // 45056 B
#define FWORDS (41 * DPB)              // 1312 u64
#define SMEM_BYTES (2 * XBYTES + FWORDS * 8)   // 100608 B -> 2 blocks/SM
#define CHUNKS (ROWS * 16)             // 2816 16B units per tile

__device__ __forceinline__ uint64_t f2fma(uint64_t a, uint64_t b, uint64_t c) {
    uint64_t r;
    asm("fma.rn.f32x2 %0, %1, %2, %3;" : "=l"(r) : "l"(a), "l"(b), "l"(c));
    return r;
}

__device__ __forceinline__ uint32_t smem_u32(const void* p) {
    uint32_t a;
    asm("{ .reg .u64 t; cvta.to.shared.u64 t, %1; cvt.u32.u64 %0, t; }"
        : "=r"(a) : "l"(p));
    return a;
}

// One dense stream, NT taps, RT=16 outputs: rows rb+2l (l=0..NT+14) from
// smem; taps from smem slab via depth-2 pipe. 16-deep ring, &15 indexing.
// Refill of row c+16 lands in the slot whose row c was last used at iter c;
// first use of row c+16 is iter c+1 r=15 (~30 issue-cyc later > 29-cyc LDS).
template<int NT>
__device__ __forceinline__ void stream_acc(uint64_t* __restrict__ acc,
                                           const uint64_t* __restrict__ sxp,
                                           int rb,
                                           const uint64_t* __restrict__ sft)
{
    uint64_t tp[2];
    tp[0] = sft[0];
    tp[1] = sft[DPB];

    uint64_t w[16];
#pragma unroll
    for (int u = 0; u < 16; ++u)
        w[u] = sxp[(rb + 2 * u) * DPB];

#pragma unroll
    for (int c = 0; c < NT; ++c) {
        const uint64_t tap = tp[c & 1];
        if (c + 2 < NT) tp[c & 1] = sft[(c + 2) * DPB];
#pragma unroll
        for (int r = 0; r < RT; ++r)
            acc[r] = f2fma(tap, w[(c + r) & 15], acc[r]);
        if (c < NT - 1)
            w[c & 15] = sxp[(rb + 2 * (c + 16)) * DPB];
    }
}

__global__ __launch_bounds__(NTH, 2)
void fsmn_kernel(const float* __restrict__ x,
                 const float* __restrict__ filt,
                 float* __restrict__ out)
{
    extern __shared__ uint64_t sm[];   // [2][ROWS][DPB] x | [41][DPB] filt
    uint64_t* const sx = sm;
    uint64_t* const sf = sm + 2 * XWORDS;

    const int tid = threadIdx.x;
    const int q0  = blockIdx.x * TPB;         // first tile index
    const int dpg = blockIdx.y * DPB;         // d-pair base
    const int b   = blockIdx.z;

    const uint64_t* __restrict__ xg =
        reinterpret_cast<const uint64_t*>(x) + (size_t)b * T_ * DPAL + dpg;
    uint64_t* __restrict__ og =
        reinterpret_cast<uint64_t*>(out) + (size_t)b * T_ * DPAL + dpg;
    const uint64_t* __restrict__ fg =
        reinterpret_cast<const uint64_t*>(filt) + dpg;

    // ---- stage filter slab into smem once: sf[k*DPB + dpl] ----
#pragma unroll
    for (int k = 0; k < 7; ++k) {
        const int i = tid + k * NTH;
        if (i < FWORDS)
            sf[i] = fg[(size_t)(i >> 5) * DPAL + (i & (DPB - 1))];
    }

    const uint32_t sbase = smem_u32(sx);

    // ---- cp.async tile prefetch: 2816 16B units over 192 threads ----
    auto prefetch = [&](int buf, int qt) {
        const int tb = qt * TT;
        const uint32_t db = sbase + (uint32_t)buf * XBYTES;
#pragma unroll
        for (int k = 0; k < 15; ++k) {
            const int u = tid + k * NTH;
            if (u < CHUNKS) {
                const int row = u >> 4;
                const int c16 = u & 15;
                const int t   = tb - 40 + row;
                const char* gp =
                    reinterpret_cast<const char*>(xg + (size_t)t * DPAL)
                    + c16 * 16;
                const uint32_t dst = db + (uint32_t)(row * DPB) * 8 + c16 * 16;
                const int ok = (t >= 0 && t < T_) ? 16 : 0;
                asm volatile("cp.async.cg.shared.global [%0], [%1], 16, %2;"
                             :: "r"(dst), "l"(gp), "r"(ok) : "memory");
            }
        }
        asm volatile("cp.async.commit_group;" ::: "memory");
    };

    const int dpl = tid & (DPB - 1);          // 0..31
    const int par = (tid >> 5) & 1;           // parity owned by this thread
    const int g   = tid >> 6;                 // 0..2 (32 t each)
    const uint64_t* __restrict__ sfp = sf + dpl;

    prefetch(0, q0);

    for (int i = 0; i < TPB; ++i) {
        if (i < TPB - 1) {
            prefetch((i + 1) & 1, q0 + i + 1);
            asm volatile("cp.async.wait_group 1;" ::: "memory");
        } else {
            asm volatile("cp.async.wait_group 0;" ::: "memory");
        }
        __syncthreads();

        const int tb = (q0 + i) * TT;
        const uint64_t* __restrict__ sxp = sx + (i & 1) * XWORDS + dpl;
        const int rb = g * 32 + par;           // smem row of x[t0-40]

        uint64_t acc[RT];
#pragma unroll
        for (int r = 0; r < RT; ++r) acc[r] = 0ull;

        // A stream: left+center taps filt[0..20] over x[t0-40+2l]
        stream_acc<21>(acc, sxp, rb, sfp);
        // B stream: right taps filt[21..40] over x[t0+1+2l]
        stream_acc<20>(acc, sxp, rb + 41, sfp + 21 * DPB);

        // ---- store 16 outputs (guard: tile 20 reaches t=2015) ----
        const int t0 = tb + g * 32 + par;
#pragma unroll
        for (int r = 0; r < RT; ++r) {
            const int t = t0 + 2 * r;
            if (t < T_) og[(size_t)t * DPAL + dpl] = acc[r];
        }
        __syncthreads();   // protect buf[i&1] before next prefetch
    }
}

extern "C" void kernel_launch(void* const* d_in, const int* in_sizes, int n_in,
                              void* d_out, int out_size)
{
    const float* x    = (const float*)d_in[0];   // [32, 2000, 512] f32
    const float* filt = (const float*)d_in[1];   // [41, 512] f32
    float* out        = (float*)d_out;           // [32, 2000, 512] f32

    cudaFuncSetAttribute(fsmn_kernel,
                         cudaFuncAttributeMaxDynamicSharedMemorySize,
                         SMEM_BYTES);

    dim3 grid(3,            // 3 groups x TPB=7 tiles -> 21 t-tiles
              DPAL / DPB,   // 8 d-pair slabs
              B_);          // 32 batch
    fsmn_kernel<<<grid, NTH, SMEM_BYTES>>>(x, filt, out);
}

// round 13
// speedup vs baseline: 1.1179x; 1.1179x over previous
#include <cuda_runtime.h>
#include <cstdint>

// FSMN depthwise strided FIR on GB300 — R13.
// R11 compute core (best: 104 regs, no spill) + PERSISTENT balanced grid.
// All prior variants (R5/R9/R11/R12) plateau at 79-86us with fma%*dur~36us:
// the per-tile pipes aren't individually binding, but every grid (768-1024
// blocks on 296 residency slots) wastes ~15% in wave-quantization tail.
// R13 launches exactly 296 blocks; block k owns units [k*U/G,(k+1)*U/G) of
// the 4608 (b, d-slab, t-tile) units (tile-major within (b,slab) so filter
// slab reloads only on slab change and x halos hit L2). cp.async x-fill is
// double-buffered ACROSS unit boundaries.
//
// out[b,t,d] = sum_{i=0..19} filt[i,d]*x[b,t-(20-i)*2,d]
//            + filt[20,d]*x[b,t,d]
//            + sum_{j=0..19} filt[21+j,d]*x[b,t+1+2j,d],  zero-padded.

#define B_    32
#define T_    2000
#define DPAL  256       // d-pairs across all of D
#define DPB   32        // d-pairs per block
#define RT    8         // outputs per parity chunk
#define NTH   224       // threads = 32 dp x 7 t-groups
#define TT    112       // t-outputs per tile (7 groups x 16)
#define NTILE 18        // ceil(2000/112) tiles per (b,slab)
#define NSLAB 8         // d-pair slabs
#define NUNIT (B_ * NSLAB * NTILE)     // 4608 work units
#define NBLK  296                      // 2 blocks x 148 SMs
#define ROWS  (TT + 80) // 192 smem rows per tile
#define XWORDS (ROWS * DPB)            // 6144 u64 per buffer
#define XBYTES (XWORDS * 8)            // 49152 B
#define FWORDS (41 * DPB)              // 1312 u64
#define SMEM_BYTES (2 * XBYTES + FWORDS * 8)   // 108800 B
#define CHUNKS (ROWS * 16)             // 3072 16B units per tile

__device__ __forceinline__ uint64_t f2fma(uint64_t a, uint64_t b, uint64_t c) {
    uint64_t r;
    asm("fma.rn.f32x2 %0, %1, %2, %3;" : "=l"(r) : "l"(a), "l"(b), "l"(c));
    return r;
}

__device__ __forceinline__ uint32_t smem_u32(const void* p) {
    uint32_t a;
    asm("{ .reg .u64 t; cvta.to.shared.u64 t, %1; cvt.u32.u64 %0, t; }"
        : "=r"(a) : "l"(p));
    return a;
}

__global__ __launch_bounds__(NTH, 2)
void fsmn_kernel(const float* __restrict__ x,
                 const float* __restrict__ filt,
                 float* __restrict__ out)
{
    extern __shared__ uint64_t sm[];   // [2][ROWS][DPB] x | [41][DPB] filt
    uint64_t* const sx = sm;
    uint64_t* const sf = sm + 2 * XWORDS;

    const int tid = threadIdx.x;
    const int bid = blockIdx.x;

    // Balanced contiguous partition of the 4608 units.
    const int lo = (int)(((long long)bid       * NUNIT) / NBLK);
    const int hi = (int)(((long long)(bid + 1) * NUNIT) / NBLK);

    const uint64_t* __restrict__ xu  = reinterpret_cast<const uint64_t*>(x);
    uint64_t* __restrict__       ou  = reinterpret_cast<uint64_t*>(out);
    const uint64_t* __restrict__ fu  = reinterpret_cast<const uint64_t*>(filt);

    const uint32_t sbase = smem_u32(sx);
    const int dpl = tid & (DPB - 1);          // 0..31
    const int g   = tid >> 5;                 // 0..6 (16 t each)
    const uint64_t* __restrict__ sfp = sf + dpl;

    // Issue a tile prefetch for unit u into buffer buf.
    auto prefetch = [&](int buf, int u) {
        const int tile = u % NTILE;
        const int bs   = u / NTILE;
        const int slab = bs & (NSLAB - 1);
        const int bb   = bs >> 3;
        const uint64_t* __restrict__ xg =
            xu + (size_t)bb * T_ * DPAL + slab * DPB;
        const int tb = tile * TT;
        const uint32_t db = sbase + (uint32_t)buf * XBYTES;
#pragma unroll
        for (int k = 0; k < 14; ++k) {
            const int uu = tid + k * NTH;
            if (uu < CHUNKS) {
                const int row = uu >> 4;
                const int c16 = uu & 15;
                const int t   = tb - 40 + row;
                const char* gp =
                    reinterpret_cast<const char*>(xg + (size_t)t * DPAL)
                    + c16 * 16;
                const uint32_t dst = db + (uint32_t)(row * DPB) * 8 + c16 * 16;
                const int ok = (t >= 0 && t < T_) ? 16 : 0;
                asm volatile("cp.async.cg.shared.global [%0], [%1], 16, %2;"
                             :: "r"(dst), "l"(gp), "r"(ok) : "memory");
            }
        }
        asm volatile("cp.async.commit_group;" ::: "memory");
    };

    int prev_slab = -1;
    prefetch(0, lo);

    for (int u = lo; u < hi; ++u) {
        const int tile = u % NTILE;
        const int bs   = u / NTILE;
        const int slab = bs & (NSLAB - 1);
        const int bb   = bs >> 3;
        const int tb   = tile * TT;
        const int buf  = (u - lo) & 1;

        uint64_t* __restrict__ og =
            ou + (size_t)bb * T_ * DPAL + slab * DPB;

        if (u + 1 < hi) {
            prefetch(buf ^ 1, u + 1);
            asm volatile("cp.async.wait_group 1;" ::: "memory");
        } else {
            asm volatile("cp.async.wait_group 0;" ::: "memory");
        }

        // Refresh the filter slab in smem when the d-slab changes.
        if (slab != prev_slab) {
            const uint64_t* __restrict__ fg = fu + slab * DPB;
#pragma unroll
            for (int k = 0; k < 6; ++k) {
                const int i = tid + k * NTH;
                if (i < FWORDS)
                    sf[i] = fg[(size_t)(i >> 5) * DPAL + (i & (DPB - 1))];
            }
        }
        prev_slab = slab;
        __syncthreads();

        const uint64_t* __restrict__ sxp = sx + buf * XWORDS + dpl;

        uint64_t acc[16];                      // [par*8 + r]
#pragma unroll
        for (int z = 0; z < 16; ++z) acc[z] = 0ull;

        // ======== A phase: left+center taps filt[0..20], both parities =====
        {
            uint64_t fL[21];
#pragma unroll
            for (int c = 0; c < 21; ++c) fL[c] = sfp[c * DPB];
#pragma unroll
            for (int par = 0; par < 2; ++par) {
                const int rb = g * 16 + par;   // smem row of x[t0-40]
                uint64_t w[RT];
#pragma unroll
                for (int uu = 0; uu < RT; ++uu)
                    w[uu] = sxp[(rb + 2 * uu) * DPB];
#pragma unroll
                for (int c = 0; c < 21; ++c) {
#pragma unroll
                    for (int r = 0; r < RT; ++r)
                        acc[par * RT + r] = f2fma(fL[c], w[(c + r) & (RT - 1)],
                                                  acc[par * RT + r]);
                    if (c < 20)
                        w[c & (RT - 1)] = sxp[(rb + 2 * (c + RT)) * DPB];
                }
            }
        }

        // ======== B phase: right taps filt[21..40], both parities ==========
        {
            uint64_t fR[20];
#pragma unroll
            for (int c = 0; c < 20; ++c) fR[c] = sfp[(21 + c) * DPB];
#pragma unroll
            for (int par = 0; par < 2; ++par) {
                const int rb = g * 16 + par + 41; // smem row of x[t0+1]
                uint64_t w[RT];
#pragma unroll
                for (int uu = 0; uu < RT; ++uu)
                    w[uu] = sxp[(rb + 2 * uu) * DPB];
#pragma unroll
                for (int c = 0; c < 20; ++c) {
#pragma unroll
                    for (int r = 0; r < RT; ++r)
                        acc[par * RT + r] = f2fma(fR[c], w[(c + r) & (RT - 1)],
                                                  acc[par * RT + r]);
                    if (c < 19)
                        w[c & (RT - 1)] = sxp[(rb + 2 * (c + RT)) * DPB];
                }
            }
        }

        // -------- store 16 outputs (guard: tile 17 reaches t=2015) ---------
#pragma unroll
        for (int par = 0; par < 2; ++par) {
            const int t0 = tb + g * 16 + par;
#pragma unroll
            for (int r = 0; r < RT; ++r) {
                const int t = t0 + 2 * r;
                if (t < T_) og[(size_t)t * DPAL + dpl] = acc[par * RT + r];
            }
        }
        __syncthreads();   // protect smem buffers before next iteration
    }
}

extern "C" void kernel_launch(void* const* d_in, const int* in_sizes, int n_in,
                              void* d_out, int out_size)
{
    const float* x    = (const float*)d_in[0];   // [32, 2000, 512] f32
    const float* filt = (const float*)d_in[1];   // [41, 512] f32
    float* out        = (float*)d_out;           // [32, 2000, 512] f32

    cudaFuncSetAttribute(fsmn_kernel,
                         cudaFuncAttributeMaxDynamicSharedMemorySize,
                         SMEM_BYTES);

    fsmn_kernel<<<NBLK, NTH, SMEM_BYTES>>>(x, filt, out);
}